// round 6
// baseline (speedup 1.0000x reference)
#include <cuda_runtime.h>
#include <cuda_bf16.h>

// BackProjNet: out[65535 - v] = SCALE * sum_{j=0..1023} x[idx[v*1024+j]] * w[v*1024+j] + bias[v]
// Inputs (metadata order): x (376832 f32), weight (67108864 f32),
//                          bias (65536 f32), indices (67108864 int32 — JAX x64 is
//                          disabled, so the requested int64 silently became int32).
// Output: 65536 f32. Flip over both axes of a 256x256 image == reversed flat index.

static constexpr int   VOXELS  = 256 * 256;   // 65536
static constexpr int   VE      = 1024;        // views * extent per voxel
static constexpr float SCALE_F = (float)(3.14159265358979323846 / 1024.0); // 2pi/(2*512*2)

__global__ __launch_bounds__(256)
void backproj_kernel(const float* __restrict__ sino,
                     const float* __restrict__ weight,
                     const float* __restrict__ bias,
                     const int*   __restrict__ indices,
                     float* __restrict__ out)
{
    const int warp = (int)((blockIdx.x * blockDim.x + threadIdx.x) >> 5);
    const int lane = threadIdx.x & 31;
    if (warp >= VOXELS) return;

    const long long base = (long long)warp * VE;

    float acc = 0.0f;

    // 8 iterations: each lane handles 4 adjacent (index, weight) pairs via
    // int4 + float4 loads. Per warp-iteration: 128 contiguous pairs ->
    // 512B index load + 512B weight load, fully coalesced. Unrolled for MLP.
    #pragma unroll
    for (int k = 0; k < 8; ++k) {
        const long long j = base + (long long)(k * 128 + lane * 4);
        const int4   i4 = *reinterpret_cast<const int4*>(indices + j);
        const float4 w4 = *reinterpret_cast<const float4*>(weight + j);
        const float s0 = __ldg(sino + i4.x);
        const float s1 = __ldg(sino + i4.y);
        const float s2 = __ldg(sino + i4.z);
        const float s3 = __ldg(sino + i4.w);
        acc = fmaf(s0, w4.x, acc);
        acc = fmaf(s1, w4.y, acc);
        acc = fmaf(s2, w4.z, acc);
        acc = fmaf(s3, w4.w, acc);
    }

    // Warp tree reduction.
    #pragma unroll
    for (int o = 16; o > 0; o >>= 1)
        acc += __shfl_xor_sync(0xffffffffu, acc, o);

    if (lane == 0) {
        out[VOXELS - 1 - warp] = acc * SCALE_F + bias[warp];
    }
}

extern "C" void kernel_launch(void* const* d_in, const int* in_sizes, int n_in,
                              void* d_out, int out_size)
{
    const float* x       = (const float*)d_in[0];
    const float* weight  = (const float*)d_in[1];
    const float* bias    = (const float*)d_in[2];
    const int*   indices = (const int*)d_in[3];
    float*       out     = (float*)d_out;

    // 65536 warps, 8 warps per block -> 8192 blocks of 256 threads.
    const int threads = 256;
    const int blocks  = (VOXELS * 32) / threads;   // 8192
    backproj_kernel<<<blocks, threads>>>(x, weight, bias, indices, out);
}